// round 2
// baseline (speedup 1.0000x reference)
#include <cuda_runtime.h>
#include <math.h>

// ---------------------------------------------------------------------------
// SpectroTFDecoder: pre-LN transformer decoder layer, fp32.
// B=4, T=1024, D=1024, H=16, DH=64, DFF=4096.
// masks are structurally fixed (causal / none) -> implemented analytically.
//
// Input order (setup_inputs dict insertion order, after bias-key pop/re-append):
//  0 x, 1 src_x, 2 mask, 3 src_mask,
//  4 ln1_g, 5 ln1_b, 6 ln2_g, 7 ln2_b, 8 ln3_g, 9 ln3_b,
//  10 sa_wq, 11 sa_wk, 12 sa_wv, 13 sa_wo, 14 ca_wq, 15 ca_wk, 16 ca_wv, 17 ca_wo,
//  18 bsa_wq, 19 bsa_wk, 20 bsa_wv, 21 bsa_wo, 22 bca_wq, 23 bca_wk, 24 bca_wv, 25 bca_wo,
//  26 ff_w1, 27 ff_b1, 28 ff_w2, 29 ff_b2
// ---------------------------------------------------------------------------

#define D_MODEL 1024
#define BATCH   4
#define TSEQ    1024
#define N_ROWS  (BATCH * TSEQ)   // 4096
#define NHEAD   16
#define DHEAD   64
#define DFF_    4096
#define LN_EPS  1e-6f

// Scratch (static device allocations are allowed)
__device__ float g_h  [N_ROWS * D_MODEL];
__device__ float g_q  [N_ROWS * D_MODEL];
__device__ float g_k  [N_ROWS * D_MODEL];
__device__ float g_v  [N_ROWS * D_MODEL];
__device__ float g_ctx[N_ROWS * D_MODEL];
__device__ float g_x1 [N_ROWS * D_MODEL];
__device__ float g_x2 [N_ROWS * D_MODEL];
__device__ float g_ff [N_ROWS * DFF_];

// ---------------------------------------------------------------------------
// LayerNorm: one block per row of 1024, 256 threads x 4 elements.
// sigma = sqrt(mean((x-mu)^2)); out = (x-mu)/(sigma+eps)*g + b
// ---------------------------------------------------------------------------
__global__ __launch_bounds__(256)
void ln_kernel(const float* __restrict__ x, const float* __restrict__ g,
               const float* __restrict__ bta, float* __restrict__ o)
{
    const int row = blockIdx.x;
    const int t = threadIdx.x;
    const float* xr = x + (size_t)row * D_MODEL;
    float4 xv = *(const float4*)(xr + t * 4);

    float s = xv.x + xv.y + xv.z + xv.w;
    __shared__ float red[8];
    #pragma unroll
    for (int off = 16; off > 0; off >>= 1) s += __shfl_xor_sync(~0u, s, off);
    if ((t & 31) == 0) red[t >> 5] = s;
    __syncthreads();
    float tot = 0.f;
    #pragma unroll
    for (int i = 0; i < 8; i++) tot += red[i];
    const float mu = tot * (1.f / 1024.f);

    const float dx0 = xv.x - mu, dx1 = xv.y - mu, dx2 = xv.z - mu, dx3 = xv.w - mu;
    float sq = dx0*dx0 + dx1*dx1 + dx2*dx2 + dx3*dx3;
    #pragma unroll
    for (int off = 16; off > 0; off >>= 1) sq += __shfl_xor_sync(~0u, sq, off);
    __syncthreads();
    if ((t & 31) == 0) red[t >> 5] = sq;
    __syncthreads();
    float tot2 = 0.f;
    #pragma unroll
    for (int i = 0; i < 8; i++) tot2 += red[i];
    const float sigma = sqrtf(tot2 * (1.f / 1024.f));
    const float inv = 1.f / (sigma + LN_EPS);

    float4 gv = *(const float4*)(g + t * 4);
    float4 bv = *(const float4*)(bta + t * 4);
    float4 ov;
    ov.x = dx0 * inv * gv.x + bv.x;
    ov.y = dx1 * inv * gv.y + bv.y;
    ov.z = dx2 * inv * gv.z + bv.z;
    ov.w = dx3 * inv * gv.w + bv.w;
    *(float4*)(o + (size_t)row * D_MODEL + t * 4) = ov;
}

// ---------------------------------------------------------------------------
// SGEMM: C[M,N] = A[M,K] @ W[K,N] + bias (+ res), optional ReLU (applied
// before residual; the two are never used together in this model).
// 128x128 tile, BK=8, 256 threads, 8x8 per-thread micro-tile, double-buffered.
// Requires M%128==0, N%128==0, K%8==0 (true for all shapes here).
// ---------------------------------------------------------------------------
template<bool RELU, bool RES>
__global__ __launch_bounds__(256, 2)
void sgemm_kernel(const float* __restrict__ A, const float* __restrict__ W,
                  const float* __restrict__ bias, const float* __restrict__ res,
                  float* __restrict__ C, int M, int N, int K)
{
    __shared__ float As[2][8][128];
    __shared__ float Bs[2][8][128];
    const int tid = threadIdx.x;
    const int bm = blockIdx.y * 128;
    const int bn = blockIdx.x * 128;

    // global-load mapping
    const int arow = tid >> 1;            // 0..127
    const int acol = (tid & 1) * 4;       // 0 or 4
    const int brow = tid >> 5;            // 0..7
    const int bcol = (tid & 31) * 4;      // 0..124

    const float* Aptr = A + (size_t)(bm + arow) * K + acol;
    const float* Bptr = W + (size_t)brow * N + bn + bcol;

    // compute mapping: 16x16 thread grid, split-N columns to avoid LDS conflicts
    const int ty = tid >> 4;
    const int tx = tid & 15;
    const int crow = ty * 8;
    const int c0 = tx * 4;
    const int c1 = 64 + tx * 4;

    float acc[8][8];
    #pragma unroll
    for (int i = 0; i < 8; i++)
        #pragma unroll
        for (int j = 0; j < 8; j++) acc[i][j] = 0.f;

    // prologue: stage 0
    {
        float4 a4 = *(const float4*)Aptr;
        float4 b4 = *(const float4*)Bptr;
        As[0][acol + 0][arow] = a4.x;
        As[0][acol + 1][arow] = a4.y;
        As[0][acol + 2][arow] = a4.z;
        As[0][acol + 3][arow] = a4.w;
        *(float4*)&Bs[0][brow][bcol] = b4;
    }
    __syncthreads();

    const int nk = K >> 3;
    for (int kt = 0; kt < nk; kt++) {
        const int cur = kt & 1;
        const int nxt = cur ^ 1;
        float4 a4n, b4n;
        const bool more = (kt + 1 < nk);
        if (more) {
            a4n = *(const float4*)(Aptr + (size_t)(kt + 1) * 8);
            b4n = *(const float4*)(Bptr + (size_t)(kt + 1) * 8 * N);
        }
        #pragma unroll
        for (int k = 0; k < 8; k++) {
            float4 arA = *(const float4*)&As[cur][k][crow];
            float4 arB = *(const float4*)&As[cur][k][crow + 4];
            float4 brA = *(const float4*)&Bs[cur][k][c0];
            float4 brB = *(const float4*)&Bs[cur][k][c1];
            float ar[8] = {arA.x, arA.y, arA.z, arA.w, arB.x, arB.y, arB.z, arB.w};
            float br[8] = {brA.x, brA.y, brA.z, brA.w, brB.x, brB.y, brB.z, brB.w};
            #pragma unroll
            for (int i = 0; i < 8; i++)
                #pragma unroll
                for (int j = 0; j < 8; j++)
                    acc[i][j] += ar[i] * br[j];
        }
        if (more) {
            As[nxt][acol + 0][arow] = a4n.x;
            As[nxt][acol + 1][arow] = a4n.y;
            As[nxt][acol + 2][arow] = a4n.z;
            As[nxt][acol + 3][arow] = a4n.w;
            *(float4*)&Bs[nxt][brow][bcol] = b4n;
        }
        __syncthreads();
    }

    // epilogue
    float bia[8];
    #pragma unroll
    for (int j = 0; j < 4; j++) {
        bia[j]     = bias[bn + c0 + j];
        bia[4 + j] = bias[bn + c1 + j];
    }
    #pragma unroll
    for (int i = 0; i < 8; i++) {
        const int row = bm + crow + i;
        float* cp = C + (size_t)row * N + bn;
        float v[8];
        #pragma unroll
        for (int j = 0; j < 8; j++) v[j] = acc[i][j] + bia[j];
        if (RELU) {
            #pragma unroll
            for (int j = 0; j < 8; j++) v[j] = fmaxf(v[j], 0.f);
        }
        if (RES) {
            const float* rp = res + (size_t)row * N + bn;
            float4 r0 = *(const float4*)(rp + c0);
            float4 r1 = *(const float4*)(rp + c1);
            v[0] += r0.x; v[1] += r0.y; v[2] += r0.z; v[3] += r0.w;
            v[4] += r1.x; v[5] += r1.y; v[6] += r1.z; v[7] += r1.w;
        }
        float4 o0 = {v[0], v[1], v[2], v[3]};
        float4 o1 = {v[4], v[5], v[6], v[7]};
        *(float4*)(cp + c0) = o0;
        *(float4*)(cp + c1) = o1;
    }
}

// ---------------------------------------------------------------------------
// Flash-style attention, fp32, DH=64.
// One block = (q-tile of 64 rows) x (one head) x (one batch). 256 threads:
// thread = (qrow = tid/4, sub = tid%4); each thread owns 16 key-cols of S
// (interleaved kc = sub + 4j) and 16 output dims (dh = sub + 4j).
// Q/K/V layout: [B*T, D] row-major with head h at column offset h*64.
// causal: only loop k-tiles <= q-tile; mask kg > qg on the diagonal tile.
// ---------------------------------------------------------------------------
#define PSQ 65   // padded row stride for Qs / KVs
#define PSP 66   // padded row stride for Ps
#define ATTN_SMEM ((64 * (PSQ + PSQ + PSP)) * (int)sizeof(float))

__global__ __launch_bounds__(256)
void attn_kernel(const float* __restrict__ Q, const float* __restrict__ Kv,
                 const float* __restrict__ Vv, float* __restrict__ O,
                 int causal)
{
    const int qt = blockIdx.x;   // q-tile (0..15)
    const int h  = blockIdx.y;   // head
    const int b  = blockIdx.z;   // batch
    const int tid = threadIdx.x;
    const int qrow = tid >> 2;   // 0..63
    const int sub  = tid & 3;    // 0..3

    const size_t base = ((size_t)b * TSEQ) * D_MODEL + (size_t)h * DHEAD;

    extern __shared__ float sm[];
    float* Qs  = sm;                  // [64][PSQ]
    float* KVs = sm + 64 * PSQ;       // [64][PSQ]  (K, then reused for V)
    float* Ps  = sm + 2 * 64 * PSQ;   // [64][PSP]

    // load Q tile (scaled by 1/sqrt(DH) up front)
    {
        const int r  = tid >> 2;
        const int cc = (tid & 3) * 16;
        const float* src = Q + base + (size_t)(qt * 64 + r) * D_MODEL + cc;
        #pragma unroll
        for (int c = 0; c < 16; c += 4) {
            float4 v4 = *(const float4*)(src + c);
            Qs[r * PSQ + cc + c + 0] = v4.x * 0.125f;
            Qs[r * PSQ + cc + c + 1] = v4.y * 0.125f;
            Qs[r * PSQ + cc + c + 2] = v4.z * 0.125f;
            Qs[r * PSQ + cc + c + 3] = v4.w * 0.125f;
        }
    }

    float m = -INFINITY, l = 0.f;
    float acc[16];
    #pragma unroll
    for (int i = 0; i < 16; i++) acc[i] = 0.f;

    const int ktEnd = causal ? qt : (TSEQ / 64 - 1);
    const int qg = qt * 64 + qrow;

    for (int kt = 0; kt <= ktEnd; kt++) {
        __syncthreads();   // prior PV reads of KVs/Ps done
        // load K tile
        {
            const int r  = tid >> 2;
            const int cc = (tid & 3) * 16;
            const float* src = Kv + base + (size_t)(kt * 64 + r) * D_MODEL + cc;
            #pragma unroll
            for (int c = 0; c < 16; c += 4) {
                float4 v4 = *(const float4*)(src + c);
                KVs[r * PSQ + cc + c + 0] = v4.x;
                KVs[r * PSQ + cc + c + 1] = v4.y;
                KVs[r * PSQ + cc + c + 2] = v4.z;
                KVs[r * PSQ + cc + c + 3] = v4.w;
            }
        }
        __syncthreads();

        // S = Q @ K^T (already scaled), causal mask, online softmax
        float s[16];
        #pragma unroll
        for (int j = 0; j < 16; j++) s[j] = 0.f;
        const float* qp = &Qs[qrow * PSQ];
        #pragma unroll 8
        for (int dd = 0; dd < 64; dd++) {
            const float qv = qp[dd];
            #pragma unroll
            for (int j = 0; j < 16; j++)
                s[j] += qv * KVs[(sub + 4 * j) * PSQ + dd];
        }
        float tmax = -INFINITY;
        const bool diag = causal && (kt == qt);
        #pragma unroll
        for (int j = 0; j < 16; j++) {
            if (diag && (kt * 64 + sub + 4 * j) > qg) s[j] = -INFINITY;
            tmax = fmaxf(tmax, s[j]);
        }
        tmax = fmaxf(tmax, __shfl_xor_sync(~0u, tmax, 1));
        tmax = fmaxf(tmax, __shfl_xor_sync(~0u, tmax, 2));
        const float mnew = fmaxf(m, tmax);
        const float corr = __expf(m - mnew);
        float lsum = 0.f;
        #pragma unroll
        for (int j = 0; j < 16; j++) {
            const float p = __expf(s[j] - mnew);
            lsum += p;
            Ps[qrow * PSP + sub + 4 * j] = p;
        }
        lsum += __shfl_xor_sync(~0u, lsum, 1);
        lsum += __shfl_xor_sync(~0u, lsum, 2);
        l = l * corr + lsum;
        m = mnew;
        #pragma unroll
        for (int i = 0; i < 16; i++) acc[i] *= corr;
        __syncthreads();   // Ps written; K reads done

        // load V tile (reuse KVs)
        {
            const int r  = tid >> 2;
            const int cc = (tid & 3) * 16;
            const float* src = Vv + base + (size_t)(kt * 64 + r) * D_MODEL + cc;
            #pragma unroll
            for (int c = 0; c < 16; c += 4) {
                float4 v4 = *(const float4*)(src + c);
                KVs[r * PSQ + cc + c + 0] = v4.x;
                KVs[r * PSQ + cc + c + 1] = v4.y;
                KVs[r * PSQ + cc + c + 2] = v4.z;
                KVs[r * PSQ + cc + c + 3] = v4.w;
            }
        }
        __syncthreads();

        // acc += P @ V
        const float* pp = &Ps[qrow * PSP];
        #pragma unroll 4
        for (int kk = 0; kk < 64; kk++) {
            const float p = pp[kk];
            const float* vp = &KVs[kk * PSQ];
            #pragma unroll
            for (int j = 0; j < 16; j++)
                acc[j] += p * vp[sub + 4 * j];
        }
    }

    const float inv = 1.f / l;
    float* op = O + base + (size_t)(qt * 64 + qrow) * D_MODEL;
    #pragma unroll
    for (int j = 0; j < 16; j++)
        op[sub + 4 * j] = acc[j] * inv;
}

// ---------------------------------------------------------------------------
// Host orchestration
// ---------------------------------------------------------------------------
extern "C" void kernel_launch(void* const* d_in, const int* in_sizes, int n_in,
                              void* d_out, int out_size)
{
    (void)in_sizes; (void)n_in; (void)out_size;
    const float* x     = (const float*)d_in[0];
    const float* src_x = (const float*)d_in[1];
    // d_in[2] (mask) and d_in[3] (src_mask) are structurally fixed; handled analytically.
    const float* ln1_g = (const float*)d_in[4];
    const float* ln1_b = (const float*)d_in[5];
    const float* ln2_g = (const float*)d_in[6];
    const float* ln2_b = (const float*)d_in[7];
    const float* ln3_g = (const float*)d_in[8];
    const float* ln3_b = (const float*)d_in[9];
    // weights: contiguous block (dict order after bias re-append)
    const float* sa_wq = (const float*)d_in[10];
    const float* sa_wk = (const float*)d_in[11];
    const float* sa_wv = (const float*)d_in[12];
    const float* sa_wo = (const float*)d_in[13];
    const float* ca_wq = (const float*)d_in[14];
    const float* ca_wk = (const float*)d_in[15];
    const float* ca_wv = (const float*)d_in[16];
    const float* ca_wo = (const float*)d_in[17];
    // biases: contiguous block
    const float* sa_bq = (const float*)d_in[18];
    const float* sa_bk = (const float*)d_in[19];
    const float* sa_bv = (const float*)d_in[20];
    const float* sa_bo = (const float*)d_in[21];
    const float* ca_bq = (const float*)d_in[22];
    const float* ca_bk = (const float*)d_in[23];
    const float* ca_bv = (const float*)d_in[24];
    const float* ca_bo = (const float*)d_in[25];
    const float* ff_w1 = (const float*)d_in[26];
    const float* ff_b1 = (const float*)d_in[27];
    const float* ff_w2 = (const float*)d_in[28];
    const float* ff_b2 = (const float*)d_in[29];
    float* out = (float*)d_out;

    float *h, *q, *k, *v, *ctx, *x1, *x2, *ff;
    cudaGetSymbolAddress((void**)&h,   g_h);
    cudaGetSymbolAddress((void**)&q,   g_q);
    cudaGetSymbolAddress((void**)&k,   g_k);
    cudaGetSymbolAddress((void**)&v,   g_v);
    cudaGetSymbolAddress((void**)&ctx, g_ctx);
    cudaGetSymbolAddress((void**)&x1,  g_x1);
    cudaGetSymbolAddress((void**)&x2,  g_x2);
    cudaGetSymbolAddress((void**)&ff,  g_ff);

    cudaFuncSetAttribute(attn_kernel,
                         cudaFuncAttributeMaxDynamicSharedMemorySize, ATTN_SMEM);

    const dim3 gD  (D_MODEL / 128, N_ROWS / 128);   // (8, 32)
    const dim3 gFF1(DFF_   / 128, N_ROWS / 128);    // (32, 32)
    const dim3 gAtt(TSEQ / 64, NHEAD, BATCH);       // (16, 16, 4)

    // ---- self-attention block ----
    ln_kernel<<<N_ROWS, 256>>>(x, ln1_g, ln1_b, h);
    sgemm_kernel<false, false><<<gD, 256>>>(h, sa_wq, sa_bq, nullptr, q, N_ROWS, D_MODEL, D_MODEL);
    sgemm_kernel<false, false><<<gD, 256>>>(h, sa_wk, sa_bk, nullptr, k, N_ROWS, D_MODEL, D_MODEL);
    sgemm_kernel<false, false><<<gD, 256>>>(h, sa_wv, sa_bv, nullptr, v, N_ROWS, D_MODEL, D_MODEL);
    attn_kernel<<<gAtt, 256, ATTN_SMEM>>>(q, k, v, ctx, /*causal=*/1);
    sgemm_kernel<false, true ><<<gD, 256>>>(ctx, sa_wo, sa_bo, x, x1, N_ROWS, D_MODEL, D_MODEL);

    // ---- cross-attention block ----
    ln_kernel<<<N_ROWS, 256>>>(x1, ln2_g, ln2_b, h);
    sgemm_kernel<false, false><<<gD, 256>>>(h,     ca_wq, ca_bq, nullptr, q, N_ROWS, D_MODEL, D_MODEL);
    sgemm_kernel<false, false><<<gD, 256>>>(src_x, ca_wk, ca_bk, nullptr, k, N_ROWS, D_MODEL, D_MODEL);
    sgemm_kernel<false, false><<<gD, 256>>>(src_x, ca_wv, ca_bv, nullptr, v, N_ROWS, D_MODEL, D_MODEL);
    attn_kernel<<<gAtt, 256, ATTN_SMEM>>>(q, k, v, ctx, /*causal=*/0);
    sgemm_kernel<false, true ><<<gD, 256>>>(ctx, ca_wo, ca_bo, x1, x2, N_ROWS, D_MODEL, D_MODEL);

    // ---- FFN block ----
    ln_kernel<<<N_ROWS, 256>>>(x2, ln3_g, ln3_b, h);
    sgemm_kernel<true,  false><<<gFF1, 256>>>(h,  ff_w1, ff_b1, nullptr, ff, N_ROWS, DFF_,    D_MODEL);
    sgemm_kernel<false, true ><<<gD,   256>>>(ff, ff_w2, ff_b2, x2,      out, N_ROWS, D_MODEL, DFF_);
}